// round 1
// baseline (speedup 1.0000x reference)
#include <cuda_runtime.h>
#include <math.h>

#define Bb 32
#define Cc 256
#define Hh 64
#define Ww 64
#define HW 4096
#define NTOT (Bb*Cc*HW)

// Scratch (allocation-free rule: __device__ globals)
__device__ float g_mid[NTOT];      // 128 MB: dwconv branch output
__device__ float g_y[NTOT];        // 128 MB: post-pointwise+pwbn
__device__ float g_ssq[Bb*Cc];     // per-(b,c) sum of squares
__device__ float g_a[Bb*Cc];       // GRN multiplicative factor

__device__ __forceinline__ float gelu_f(float v) {
    return 0.5f * v * (1.0f + erff(v * 0.7071067811865475f));
}

// ---------------------------------------------------------------------------
// K1: fused dwconv(3,5,7) + BN + GELU + average -> g_mid
// One block per (b,c) plane. 70x70 haloed tile in smem (stride 72 for
// float4-aligned row reads). Each thread computes 4 runs of 4 pixels.
// Also zeroes g_ssq (grid == B*C entries).
// ---------------------------------------------------------------------------
__global__ __launch_bounds__(256) void k_dwconv(
    const float* __restrict__ x,
    const float* __restrict__ w3,
    const float* __restrict__ b3w, const float* __restrict__ b3b,
    const float* __restrict__ b3m, const float* __restrict__ b3v,
    const float* __restrict__ w5,
    const float* __restrict__ b5w, const float* __restrict__ b5b,
    const float* __restrict__ b5m, const float* __restrict__ b5v,
    const float* __restrict__ w7,
    const float* __restrict__ b7w, const float* __restrict__ b7b,
    const float* __restrict__ b7m, const float* __restrict__ b7v)
{
    __shared__ float tile[70 * 72];
    __shared__ float sw3[9], sw5[25], sw7[49];

    const int blk = blockIdx.x;        // b*256 + c
    const int c   = blk & 255;
    const int tid = threadIdx.x;

    if (tid == 0) g_ssq[blk] = 0.0f;   // zero accumulator for K2

    const float* __restrict__ xp = x + (size_t)blk * HW;

    if (tid < 9)        sw3[tid]      = w3[c * 9 + tid];
    else if (tid < 34)  sw5[tid - 9]  = w5[c * 25 + (tid - 9)];
    else if (tid < 83)  sw7[tid - 34] = w7[c * 49 + (tid - 34)];

    // Haloed tile load (zero padding)
    for (int idx = tid; idx < 70 * 70; idx += 256) {
        int sy = idx / 70, sx = idx - sy * 70;
        int gy = sy - 3, gx = sx - 3;
        float v = 0.0f;
        if ((unsigned)gy < 64u && (unsigned)gx < 64u) v = xp[gy * 64 + gx];
        tile[sy * 72 + sx] = v;
    }

    const float sc3 = b3w[c] * rsqrtf(b3v[c] + 1e-5f);
    const float sh3 = b3b[c] - b3m[c] * sc3;
    const float sc5 = b5w[c] * rsqrtf(b5v[c] + 1e-5f);
    const float sh5 = b5b[c] - b5m[c] * sc5;
    const float sc7 = b7w[c] * rsqrtf(b7v[c] + 1e-5f);
    const float sh7 = b7b[c] - b7m[c] * sc7;

    __syncthreads();

    const int tx = tid & 15;     // column group -> x0 = tx*4
    const int r0 = tid >> 4;     // base row 0..15
    float* __restrict__ midp = g_mid + (size_t)blk * HW;
    const float inv3 = (1.0f / 3.0f);

    #pragma unroll
    for (int rit = 0; rit < 4; rit++) {
        const int y = r0 + rit * 16;
        float a3[4] = {0.f, 0.f, 0.f, 0.f};
        float a5[4] = {0.f, 0.f, 0.f, 0.f};
        float a7[4] = {0.f, 0.f, 0.f, 0.f};

        #pragma unroll
        for (int ky = 0; ky < 7; ky++) {
            const float* rowp = &tile[(y + ky) * 72 + tx * 4];
            float4 v0 = *(const float4*)(rowp);
            float4 v1 = *(const float4*)(rowp + 4);
            float4 v2 = *(const float4*)(rowp + 8);
            float f[12];
            f[0]=v0.x; f[1]=v0.y; f[2]=v0.z; f[3]=v0.w;
            f[4]=v1.x; f[5]=v1.y; f[6]=v1.z; f[7]=v1.w;
            f[8]=v2.x; f[9]=v2.y; f[10]=v2.z; f[11]=v2.w;

            #pragma unroll
            for (int kx = 0; kx < 7; kx++) {
                const float w = sw7[ky * 7 + kx];
                #pragma unroll
                for (int j = 0; j < 4; j++) a7[j] += f[j + kx] * w;
            }
            if (ky >= 1 && ky <= 5) {
                #pragma unroll
                for (int kx = 0; kx < 5; kx++) {
                    const float w = sw5[(ky - 1) * 5 + kx];
                    #pragma unroll
                    for (int j = 0; j < 4; j++) a5[j] += f[j + 1 + kx] * w;
                }
            }
            if (ky >= 2 && ky <= 4) {
                #pragma unroll
                for (int kx = 0; kx < 3; kx++) {
                    const float w = sw3[(ky - 2) * 3 + kx];
                    #pragma unroll
                    for (int j = 0; j < 4; j++) a3[j] += f[j + 2 + kx] * w;
                }
            }
        }

        float4 o;
        float* op = (float*)&o;
        #pragma unroll
        for (int j = 0; j < 4; j++) {
            float v = gelu_f(a3[j] * sc3 + sh3)
                    + gelu_f(a5[j] * sc5 + sh5)
                    + gelu_f(a7[j] * sc7 + sh7);
            op[j] = v * inv3;
        }
        *(float4*)&midp[y * 64 + tx * 4] = o;
    }
}

// ---------------------------------------------------------------------------
// K2: per-batch GEMM  y[b,o,p] = sum_c W[o,c] * mid[b,c,p], fused pwbn,
// fused per-(b,o) sum-of-squares reduction (atomicAdd into g_ssq).
// 128x128 tile, BK=16, 8x8 microtiles, 256 threads.
// ---------------------------------------------------------------------------
__global__ __launch_bounds__(256) void k_pwgemm(
    const float* __restrict__ Wp,
    const float* __restrict__ pbw, const float* __restrict__ pbb,
    const float* __restrict__ pbm, const float* __restrict__ pbv)
{
    __shared__ float As[16][128];      // As[k][o]
    __shared__ float Bs[16][128];      // Bs[k][p]
    __shared__ float red[128][17];     // ssq reduction (padded)

    const int b     = blockIdx.z;
    const int pBase = blockIdx.x * 128;
    const int oBase = blockIdx.y * 128;
    const float* __restrict__ Mb = g_mid + (size_t)b * Cc * HW;

    const int tid = threadIdx.x;
    const int tx = tid & 15, ty = tid >> 4;

    float acc[8][8];
    #pragma unroll
    for (int i = 0; i < 8; i++)
        #pragma unroll
        for (int j = 0; j < 8; j++) acc[i][j] = 0.0f;

    for (int k0 = 0; k0 < 256; k0 += 16) {
        #pragma unroll
        for (int i = 0; i < 2; i++) {
            int e = tid + i * 256;
            int row = e >> 2, c4 = e & 3;     // 4 float4 per 16-wide row
            float4 av = *(const float4*)&Wp[(size_t)(oBase + row) * 256 + k0 + c4 * 4];
            As[c4 * 4 + 0][row] = av.x;
            As[c4 * 4 + 1][row] = av.y;
            As[c4 * 4 + 2][row] = av.z;
            As[c4 * 4 + 3][row] = av.w;
        }
        #pragma unroll
        for (int i = 0; i < 2; i++) {
            int e = tid + i * 256;
            int row = e >> 5, c4 = e & 31;    // 32 float4 per 128-wide row
            *(float4*)&Bs[row][c4 * 4] =
                *(const float4*)&Mb[(size_t)(k0 + row) * HW + pBase + c4 * 4];
        }
        __syncthreads();

        #pragma unroll
        for (int kk = 0; kk < 16; kk++) {
            float4 a0 = *(const float4*)&As[kk][ty * 8];
            float4 a1 = *(const float4*)&As[kk][ty * 8 + 4];
            float4 b0 = *(const float4*)&Bs[kk][tx * 8];
            float4 b1 = *(const float4*)&Bs[kk][tx * 8 + 4];
            float ra[8] = {a0.x, a0.y, a0.z, a0.w, a1.x, a1.y, a1.z, a1.w};
            float rb[8] = {b0.x, b0.y, b0.z, b0.w, b1.x, b1.y, b1.z, b1.w};
            #pragma unroll
            for (int i = 0; i < 8; i++)
                #pragma unroll
                for (int j = 0; j < 8; j++) acc[i][j] += ra[i] * rb[j];
        }
        __syncthreads();
    }

    float* __restrict__ yb = g_y + (size_t)b * Cc * HW;
    #pragma unroll
    for (int i = 0; i < 8; i++) {
        const int o = oBase + ty * 8 + i;
        const float sc = pbw[o] * rsqrtf(pbv[o] + 1e-5f);
        const float sh = pbb[o] - pbm[o] * sc;
        float4 o0, o1;
        float ss = 0.0f, v;
        v = acc[i][0]*sc + sh; o0.x = v; ss += v*v;
        v = acc[i][1]*sc + sh; o0.y = v; ss += v*v;
        v = acc[i][2]*sc + sh; o0.z = v; ss += v*v;
        v = acc[i][3]*sc + sh; o0.w = v; ss += v*v;
        v = acc[i][4]*sc + sh; o1.x = v; ss += v*v;
        v = acc[i][5]*sc + sh; o1.y = v; ss += v*v;
        v = acc[i][6]*sc + sh; o1.z = v; ss += v*v;
        v = acc[i][7]*sc + sh; o1.w = v; ss += v*v;
        *(float4*)&yb[(size_t)o * HW + pBase + tx * 8]     = o0;
        *(float4*)&yb[(size_t)o * HW + pBase + tx * 8 + 4] = o1;
        red[ty * 8 + i][tx] = ss;
    }
    __syncthreads();
    if (tid < 128) {
        float s = 0.0f;
        #pragma unroll
        for (int t = 0; t < 16; t++) s += red[tid][t];
        atomicAdd(&g_ssq[b * Cc + oBase + tid], s);
    }
}

// ---------------------------------------------------------------------------
// K3: GRN factor per (b,c): Gx = sqrt(ssq), Nx = Gx/(mean_c Gx + eps),
// a = 1 + gamma*Nx
// ---------------------------------------------------------------------------
__global__ __launch_bounds__(256) void k_grn(const float* __restrict__ gamma)
{
    __shared__ float sh[256];
    const int b = blockIdx.x;
    const int c = threadIdx.x;
    const float Gx = sqrtf(g_ssq[b * Cc + c]);
    sh[c] = Gx;
    __syncthreads();
    #pragma unroll
    for (int s = 128; s > 0; s >>= 1) {
        if (c < s) sh[c] += sh[c + s];
        __syncthreads();
    }
    const float mean = sh[0] * (1.0f / 256.0f);
    const float Nx = Gx / (mean + 1e-6f);
    g_a[b * Cc + c] = 1.0f + gamma[c] * Nx;
}

// ---------------------------------------------------------------------------
// K4: out = gelu(y * a[b,c] + beta[c] + x), vectorized float4
// ---------------------------------------------------------------------------
__global__ __launch_bounds__(256) void k_final(
    const float* __restrict__ x,
    const float* __restrict__ beta,
    float* __restrict__ out)
{
    const int i4 = blockIdx.x * 256 + threadIdx.x;   // NTOT/4 total
    const int bc = i4 >> 10;                          // 1024 float4 per (b,c)
    const int c  = bc & 255;
    const float a  = g_a[bc];
    const float bt = beta[c];
    float4 yv = ((const float4*)g_y)[i4];
    float4 xv = ((const float4*)x)[i4];
    float4 ov;
    ov.x = gelu_f(yv.x * a + bt + xv.x);
    ov.y = gelu_f(yv.y * a + bt + xv.y);
    ov.z = gelu_f(yv.z * a + bt + xv.z);
    ov.w = gelu_f(yv.w * a + bt + xv.w);
    ((float4*)out)[i4] = ov;
}

// ---------------------------------------------------------------------------
extern "C" void kernel_launch(void* const* d_in, const int* in_sizes, int n_in,
                              void* d_out, int out_size)
{
    const float* x    = (const float*)d_in[0];
    const float* w3   = (const float*)d_in[1];
    const float* b3w  = (const float*)d_in[2];
    const float* b3b  = (const float*)d_in[3];
    const float* b3m  = (const float*)d_in[4];
    const float* b3v  = (const float*)d_in[5];
    const float* w5   = (const float*)d_in[6];
    const float* b5w  = (const float*)d_in[7];
    const float* b5b  = (const float*)d_in[8];
    const float* b5m  = (const float*)d_in[9];
    const float* b5v  = (const float*)d_in[10];
    const float* w7   = (const float*)d_in[11];
    const float* b7w  = (const float*)d_in[12];
    const float* b7b  = (const float*)d_in[13];
    const float* b7m  = (const float*)d_in[14];
    const float* b7v  = (const float*)d_in[15];
    const float* pw   = (const float*)d_in[16];
    const float* pbw  = (const float*)d_in[17];
    const float* pbb  = (const float*)d_in[18];
    const float* pbm  = (const float*)d_in[19];
    const float* pbv  = (const float*)d_in[20];
    const float* grng = (const float*)d_in[21];
    const float* grnb = (const float*)d_in[22];

    k_dwconv<<<Bb * Cc, 256>>>(x, w3, b3w, b3b, b3m, b3v,
                               w5, b5w, b5b, b5m, b5v,
                               w7, b7w, b7b, b7m, b7v);

    dim3 g2(HW / 128, Cc / 128, Bb);   // (32, 2, 32)
    k_pwgemm<<<g2, 256>>>(pw, pbw, pbb, pbm, pbv);

    k_grn<<<Bb, 256>>>(grng);

    k_final<<<NTOT / 4 / 256, 256>>>(x, grnb, (float*)d_out);
}

// round 3
// speedup vs baseline: 1.4499x; 1.4499x over previous
#include <cuda_runtime.h>
#include <cuda_bf16.h>
#include <stdint.h>
#include <math.h>

#define Bb 32
#define Cc 256
#define Hh 64
#define Ww 64
#define HW 4096
#define NTOT (Bb*Cc*HW)

typedef unsigned int u32;

// Scratch (allocation-free rule: __device__ globals)
__device__ __nv_bfloat16 g_mh[NTOT];   // 64 MB: dwconv output, bf16 hi
__device__ __nv_bfloat16 g_ml[NTOT];   // 64 MB: dwconv output, bf16 lo (residual)
__device__ __nv_bfloat16 g_wh[Cc*Cc];  // pointwise W, bf16 hi
__device__ __nv_bfloat16 g_wl[Cc*Cc];  // pointwise W, bf16 lo
__device__ float g_y[NTOT];            // 128 MB: post-pointwise+pwbn
__device__ float g_ssq[Bb*Cc];         // per-(b,c) sum of squares
__device__ float g_a[Bb*Cc];           // GRN multiplicative factor

__device__ __forceinline__ float gelu_f(float v) {
    return 0.5f * v * (1.0f + erff(v * 0.7071067811865475f));
}

__device__ __forceinline__ u32 smem_u32(const void* p) {
    return (u32)__cvta_generic_to_shared(p);
}

__device__ __forceinline__ void ldsm_x4(u32& r0, u32& r1, u32& r2, u32& r3, u32 a) {
    asm volatile("ldmatrix.sync.aligned.m8n8.x4.shared.b16 {%0,%1,%2,%3},[%4];\n"
                 : "=r"(r0), "=r"(r1), "=r"(r2), "=r"(r3) : "r"(a));
}
__device__ __forceinline__ void ldsm_x4t(u32& r0, u32& r1, u32& r2, u32& r3, u32 a) {
    asm volatile("ldmatrix.sync.aligned.m8n8.x4.trans.shared.b16 {%0,%1,%2,%3},[%4];\n"
                 : "=r"(r0), "=r"(r1), "=r"(r2), "=r"(r3) : "r"(a));
}
__device__ __forceinline__ void mma_bf16(float* c, const u32* a, const u32* bq) {
    asm volatile(
        "mma.sync.aligned.m16n8k16.row.col.f32.bf16.bf16.f32 "
        "{%0,%1,%2,%3},{%4,%5,%6,%7},{%8,%9},{%0,%1,%2,%3};\n"
        : "+f"(c[0]), "+f"(c[1]), "+f"(c[2]), "+f"(c[3])
        : "r"(a[0]), "r"(a[1]), "r"(a[2]), "r"(a[3]), "r"(bq[0]), "r"(bq[1]));
}

// ---------------------------------------------------------------------------
// K0: split pointwise weight into bf16 hi/lo (tiny)
// ---------------------------------------------------------------------------
__global__ __launch_bounds__(256) void k_splitW(const float* __restrict__ W)
{
    int i = blockIdx.x * 256 + threadIdx.x;
    float v = W[i];
    __nv_bfloat16 h = __float2bfloat16(v);
    g_wh[i] = h;
    g_wl[i] = __float2bfloat16(v - __bfloat162float(h));
}

// ---------------------------------------------------------------------------
// K1: fused dwconv(3,5,7) + BN + GELU + average -> g_mh/g_ml (bf16 split)
// One block per (b,c) plane. 70x70 haloed tile in smem. Also zeroes g_ssq.
// ---------------------------------------------------------------------------
__global__ __launch_bounds__(256) void k_dwconv(
    const float* __restrict__ x,
    const float* __restrict__ w3,
    const float* __restrict__ b3w, const float* __restrict__ b3b,
    const float* __restrict__ b3m, const float* __restrict__ b3v,
    const float* __restrict__ w5,
    const float* __restrict__ b5w, const float* __restrict__ b5b,
    const float* __restrict__ b5m, const float* __restrict__ b5v,
    const float* __restrict__ w7,
    const float* __restrict__ b7w, const float* __restrict__ b7b,
    const float* __restrict__ b7m, const float* __restrict__ b7v)
{
    __shared__ float tile[70 * 72];
    __shared__ float sw3[9], sw5[25], sw7[49];

    const int blk = blockIdx.x;        // b*256 + c
    const int c   = blk & 255;
    const int tid = threadIdx.x;

    if (tid == 0) g_ssq[blk] = 0.0f;

    const float* __restrict__ xp = x + (size_t)blk * HW;

    if (tid < 9)        sw3[tid]      = w3[c * 9 + tid];
    else if (tid < 34)  sw5[tid - 9]  = w5[c * 25 + (tid - 9)];
    else if (tid < 83)  sw7[tid - 34] = w7[c * 49 + (tid - 34)];

    for (int idx = tid; idx < 70 * 70; idx += 256) {
        int sy = idx / 70, sx = idx - sy * 70;
        int gy = sy - 3, gx = sx - 3;
        float v = 0.0f;
        if ((unsigned)gy < 64u && (unsigned)gx < 64u) v = xp[gy * 64 + gx];
        tile[sy * 72 + sx] = v;
    }

    const float sc3 = b3w[c] * rsqrtf(b3v[c] + 1e-5f);
    const float sh3 = b3b[c] - b3m[c] * sc3;
    const float sc5 = b5w[c] * rsqrtf(b5v[c] + 1e-5f);
    const float sh5 = b5b[c] - b5m[c] * sc5;
    const float sc7 = b7w[c] * rsqrtf(b7v[c] + 1e-5f);
    const float sh7 = b7b[c] - b7m[c] * sc7;

    __syncthreads();

    const int tx = tid & 15;
    const int r0 = tid >> 4;
    const float inv3 = (1.0f / 3.0f);

    #pragma unroll
    for (int rit = 0; rit < 4; rit++) {
        const int y = r0 + rit * 16;
        float a3[4] = {0.f, 0.f, 0.f, 0.f};
        float a5[4] = {0.f, 0.f, 0.f, 0.f};
        float a7[4] = {0.f, 0.f, 0.f, 0.f};

        #pragma unroll
        for (int ky = 0; ky < 7; ky++) {
            const float* rowp = &tile[(y + ky) * 72 + tx * 4];
            float4 v0 = *(const float4*)(rowp);
            float4 v1 = *(const float4*)(rowp + 4);
            float4 v2 = *(const float4*)(rowp + 8);
            float f[12];
            f[0]=v0.x; f[1]=v0.y; f[2]=v0.z; f[3]=v0.w;
            f[4]=v1.x; f[5]=v1.y; f[6]=v1.z; f[7]=v1.w;
            f[8]=v2.x; f[9]=v2.y; f[10]=v2.z; f[11]=v2.w;

            #pragma unroll
            for (int kx = 0; kx < 7; kx++) {
                const float w = sw7[ky * 7 + kx];
                #pragma unroll
                for (int j = 0; j < 4; j++) a7[j] += f[j + kx] * w;
            }
            if (ky >= 1 && ky <= 5) {
                #pragma unroll
                for (int kx = 0; kx < 5; kx++) {
                    const float w = sw5[(ky - 1) * 5 + kx];
                    #pragma unroll
                    for (int j = 0; j < 4; j++) a5[j] += f[j + 1 + kx] * w;
                }
            }
            if (ky >= 2 && ky <= 4) {
                #pragma unroll
                for (int kx = 0; kx < 3; kx++) {
                    const float w = sw3[(ky - 2) * 3 + kx];
                    #pragma unroll
                    for (int j = 0; j < 4; j++) a3[j] += f[j + 2 + kx] * w;
                }
            }
        }

        __nv_bfloat16 hh[4], ll[4];
        #pragma unroll
        for (int j = 0; j < 4; j++) {
            float v = gelu_f(a3[j] * sc3 + sh3)
                    + gelu_f(a5[j] * sc5 + sh5)
                    + gelu_f(a7[j] * sc7 + sh7);
            v *= inv3;
            hh[j] = __float2bfloat16(v);
            ll[j] = __float2bfloat16(v - __bfloat162float(hh[j]));
        }
        size_t off = (size_t)blk * HW + y * 64 + tx * 4;
        ((__nv_bfloat162*)&g_mh[off])[0] = __halves2bfloat162(hh[0], hh[1]);
        ((__nv_bfloat162*)&g_mh[off])[1] = __halves2bfloat162(hh[2], hh[3]);
        ((__nv_bfloat162*)&g_ml[off])[0] = __halves2bfloat162(ll[0], ll[1]);
        ((__nv_bfloat162*)&g_ml[off])[1] = __halves2bfloat162(ll[2], ll[3]);
    }
}

// ---------------------------------------------------------------------------
// K2: tensor-core GEMM (split-bf16, 3 mma terms), fused pwbn + ssq.
// Block tile 128(M=o) x 128(N=p), BK=32. 8 warps: 2(M) x 4(N), warp 64x32.
// ---------------------------------------------------------------------------
__global__ __launch_bounds__(256) void k_pwgemm(
    const float* __restrict__ pbw, const float* __restrict__ pbb,
    const float* __restrict__ pbm, const float* __restrict__ pbv)
{
    __shared__ __nv_bfloat16 As[2][128][40];   // [comp][m][k]
    __shared__ __nv_bfloat16 Bs[2][32][136];   // [comp][k][n]

    const int b     = blockIdx.z;
    const int nBase = blockIdx.x * 128;
    const int mBase = blockIdx.y * 128;

    const int tid  = threadIdx.x;
    const int lane = tid & 31;
    const int warp = tid >> 5;
    const int warp_m = warp >> 2;          // 0..1
    const int warp_n = warp & 3;           // 0..3

    const __nv_bfloat16* __restrict__ Mh = g_mh + (size_t)b * Cc * HW;
    const __nv_bfloat16* __restrict__ Ml = g_ml + (size_t)b * Cc * HW;

    float acc[4][4][4];
    #pragma unroll
    for (int i = 0; i < 4; i++)
        #pragma unroll
        for (int j = 0; j < 4; j++)
            #pragma unroll
            for (int q = 0; q < 4; q++) acc[i][j][q] = 0.0f;

    for (int k0 = 0; k0 < 256; k0 += 32) {
        #pragma unroll
        for (int comp = 0; comp < 2; comp++) {
            const __nv_bfloat16* Wc = comp ? g_wl : g_wh;
            #pragma unroll
            for (int i = 0; i < 2; i++) {
                int e = i * 256 + tid;
                int row = e >> 2, seg = e & 3;
                *(uint4*)&As[comp][row][seg * 8] =
                    *(const uint4*)&Wc[(size_t)(mBase + row) * 256 + k0 + seg * 8];
            }
            const __nv_bfloat16* Mc = comp ? Ml : Mh;
            #pragma unroll
            for (int i = 0; i < 2; i++) {
                int e = i * 256 + tid;
                int row = e >> 4, seg = e & 15;
                *(uint4*)&Bs[comp][row][seg * 8] =
                    *(const uint4*)&Mc[(size_t)(k0 + row) * HW + nBase + seg * 8];
            }
        }
        __syncthreads();

        #pragma unroll
        for (int ks = 0; ks < 32; ks += 16) {
            u32 ah[4][4], al[4][4];
            const int a_m = warp_m * 64 + (lane & 15);
            const int a_k = ks + ((lane >> 4) << 3);
            #pragma unroll
            for (int fm = 0; fm < 4; fm++) {
                ldsm_x4(ah[fm][0], ah[fm][1], ah[fm][2], ah[fm][3],
                        smem_u32(&As[0][a_m + fm * 16][a_k]));
                ldsm_x4(al[fm][0], al[fm][1], al[fm][2], al[fm][3],
                        smem_u32(&As[1][a_m + fm * 16][a_k]));
            }
            u32 bh[4][2], bl[4][2];
            const int b_k = ks + (lane & 15);
            const int b_n = warp_n * 32 + ((lane >> 4) << 3);
            #pragma unroll
            for (int g = 0; g < 2; g++) {
                u32 r0, r1, r2, r3;
                ldsm_x4t(r0, r1, r2, r3, smem_u32(&Bs[0][b_k][b_n + g * 16]));
                bh[g*2][0] = r0; bh[g*2][1] = r1; bh[g*2+1][0] = r2; bh[g*2+1][1] = r3;
                ldsm_x4t(r0, r1, r2, r3, smem_u32(&Bs[1][b_k][b_n + g * 16]));
                bl[g*2][0] = r0; bl[g*2][1] = r1; bl[g*2+1][0] = r2; bl[g*2+1][1] = r3;
            }
            #pragma unroll
            for (int fm = 0; fm < 4; fm++)
                #pragma unroll
                for (int fn = 0; fn < 4; fn++) {
                    mma_bf16(acc[fm][fn], ah[fm], bh[fn]);
                    mma_bf16(acc[fm][fn], ah[fm], bl[fn]);
                    mma_bf16(acc[fm][fn], al[fm], bh[fn]);
                }
        }
        __syncthreads();
    }

    // Epilogue: pwbn + store + ssq
    float* __restrict__ yb = g_y + (size_t)b * Cc * HW;
    const int row  = lane >> 2;
    const int colq = (lane & 3) * 2;

    #pragma unroll
    for (int fm = 0; fm < 4; fm++) {
        const int o0 = mBase + warp_m * 64 + fm * 16 + row;
        const int o1 = o0 + 8;
        const float sc0 = pbw[o0] * rsqrtf(pbv[o0] + 1e-5f);
        const float sh0 = pbb[o0] - pbm[o0] * sc0;
        const float sc1 = pbw[o1] * rsqrtf(pbv[o1] + 1e-5f);
        const float sh1 = pbb[o1] - pbm[o1] * sc1;
        float ss0 = 0.0f, ss1 = 0.0f;
        #pragma unroll
        for (int fn = 0; fn < 4; fn++) {
            const int p = nBase + warp_n * 32 + fn * 8 + colq;
            float v0 = acc[fm][fn][0] * sc0 + sh0;
            float v1 = acc[fm][fn][1] * sc0 + sh0;
            float v2 = acc[fm][fn][2] * sc1 + sh1;
            float v3 = acc[fm][fn][3] * sc1 + sh1;
            ss0 += v0 * v0 + v1 * v1;
            ss1 += v2 * v2 + v3 * v3;
            *(float2*)&yb[(size_t)o0 * HW + p] = make_float2(v0, v1);
            *(float2*)&yb[(size_t)o1 * HW + p] = make_float2(v2, v3);
        }
        ss0 += __shfl_xor_sync(0xffffffffu, ss0, 1);
        ss0 += __shfl_xor_sync(0xffffffffu, ss0, 2);
        ss1 += __shfl_xor_sync(0xffffffffu, ss1, 1);
        ss1 += __shfl_xor_sync(0xffffffffu, ss1, 2);
        if ((lane & 3) == 0) {
            atomicAdd(&g_ssq[b * Cc + o0], ss0);
            atomicAdd(&g_ssq[b * Cc + o1], ss1);
        }
    }
}

// ---------------------------------------------------------------------------
// K3: GRN factor per (b,c)
// ---------------------------------------------------------------------------
__global__ __launch_bounds__(256) void k_grn(const float* __restrict__ gamma)
{
    __shared__ float sh[256];
    const int b = blockIdx.x;
    const int c = threadIdx.x;
    const float Gx = sqrtf(g_ssq[b * Cc + c]);
    sh[c] = Gx;
    __syncthreads();
    #pragma unroll
    for (int s = 128; s > 0; s >>= 1) {
        if (c < s) sh[c] += sh[c + s];
        __syncthreads();
    }
    const float mean = sh[0] * (1.0f / 256.0f);
    const float Nx = Gx / (mean + 1e-6f);
    g_a[b * Cc + c] = 1.0f + gamma[c] * Nx;
}

// ---------------------------------------------------------------------------
// K4: out = gelu(y * a[b,c] + beta[c] + x)
// ---------------------------------------------------------------------------
__global__ __launch_bounds__(256) void k_final(
    const float* __restrict__ x,
    const float* __restrict__ beta,
    float* __restrict__ out)
{
    const int i4 = blockIdx.x * 256 + threadIdx.x;
    const int bc = i4 >> 10;
    const int c  = bc & 255;
    const float a  = g_a[bc];
    const float bt = beta[c];
    float4 yv = ((const float4*)g_y)[i4];
    float4 xv = ((const float4*)x)[i4];
    float4 ov;
    ov.x = gelu_f(yv.x * a + bt + xv.x);
    ov.y = gelu_f(yv.y * a + bt + xv.y);
    ov.z = gelu_f(yv.z * a + bt + xv.z);
    ov.w = gelu_f(yv.w * a + bt + xv.w);
    ((float4*)out)[i4] = ov;
}

// ---------------------------------------------------------------------------
extern "C" void kernel_launch(void* const* d_in, const int* in_sizes, int n_in,
                              void* d_out, int out_size)
{
    const float* x    = (const float*)d_in[0];
    const float* w3   = (const float*)d_in[1];
    const float* b3w  = (const float*)d_in[2];
    const float* b3b  = (const float*)d_in[3];
    const float* b3m  = (const float*)d_in[4];
    const float* b3v  = (const float*)d_in[5];
    const float* w5   = (const float*)d_in[6];
    const float* b5w  = (const float*)d_in[7];
    const float* b5b  = (const float*)d_in[8];
    const float* b5m  = (const float*)d_in[9];
    const float* b5v  = (const float*)d_in[10];
    const float* w7   = (const float*)d_in[11];
    const float* b7w  = (const float*)d_in[12];
    const float* b7b  = (const float*)d_in[13];
    const float* b7m  = (const float*)d_in[14];
    const float* b7v  = (const float*)d_in[15];
    const float* pw   = (const float*)d_in[16];
    const float* pbw  = (const float*)d_in[17];
    const float* pbb  = (const float*)d_in[18];
    const float* pbm  = (const float*)d_in[19];
    const float* pbv  = (const float*)d_in[20];
    const float* grng = (const float*)d_in[21];
    const float* grnb = (const float*)d_in[22];

    k_splitW<<<Cc * Cc / 256, 256>>>(pw);

    k_dwconv<<<Bb * Cc, 256>>>(x, w3, b3w, b3b, b3m, b3v,
                               w5, b5w, b5b, b5m, b5v,
                               w7, b7w, b7b, b7m, b7v);

    dim3 g2(HW / 128, Cc / 128, Bb);   // (32, 2, 32)
    k_pwgemm<<<g2, 256>>>(pbw, pbb, pbm, pbv);

    k_grn<<<Bb, 256>>>(grng);

    k_final<<<NTOT / 4 / 256, 256>>>(x, grnb, (float*)d_out);
}

// round 5
// speedup vs baseline: 1.6220x; 1.1188x over previous
#include <cuda_runtime.h>
#include <cuda_fp16.h>
#include <stdint.h>
#include <math.h>

#define Bb 32
#define Cc 256
#define Hh 64
#define Ww 64
#define HW 4096
#define NTOT (Bb*Cc*HW)

typedef unsigned int u32;

// Scratch (allocation-free rule: __device__ globals)
__device__ __half g_mid[NTOT];         // 64 MB: dwconv output, fp16
__device__ __half g_wh[Cc*Cc];         // pointwise W, fp16 hi
__device__ __half g_wl[Cc*Cc];         // pointwise W, fp16 lo
__device__ float g_y[NTOT];            // 128 MB: post-pointwise+pwbn
__device__ float g_ssq[Bb*Cc];         // per-(b,c) sum of squares
__device__ float g_a[Bb*Cc];           // GRN multiplicative factor

__device__ __forceinline__ float gelu_f(float v) {
    return 0.5f * v * (1.0f + erff(v * 0.7071067811865475f));
}

__device__ __forceinline__ u32 smem_u32(const void* p) {
    return (u32)__cvta_generic_to_shared(p);
}

__device__ __forceinline__ void ldsm_x4(u32& r0, u32& r1, u32& r2, u32& r3, u32 a) {
    asm volatile("ldmatrix.sync.aligned.m8n8.x4.shared.b16 {%0,%1,%2,%3},[%4];\n"
                 : "=r"(r0), "=r"(r1), "=r"(r2), "=r"(r3) : "r"(a));
}
__device__ __forceinline__ void ldsm_x4t(u32& r0, u32& r1, u32& r2, u32& r3, u32 a) {
    asm volatile("ldmatrix.sync.aligned.m8n8.x4.trans.shared.b16 {%0,%1,%2,%3},[%4];\n"
                 : "=r"(r0), "=r"(r1), "=r"(r2), "=r"(r3) : "r"(a));
}
__device__ __forceinline__ void mma_f16(float* c, const u32* a, const u32* bq) {
    asm volatile(
        "mma.sync.aligned.m16n8k16.row.col.f32.f16.f16.f32 "
        "{%0,%1,%2,%3},{%4,%5,%6,%7},{%8,%9},{%0,%1,%2,%3};\n"
        : "+f"(c[0]), "+f"(c[1]), "+f"(c[2]), "+f"(c[3])
        : "r"(a[0]), "r"(a[1]), "r"(a[2]), "r"(a[3]), "r"(bq[0]), "r"(bq[1]));
}

#define CP_ASYNC16(dst, src) \
    asm volatile("cp.async.cg.shared.global [%0], [%1], 16;" :: "r"(dst), "l"(src))
#define CP_COMMIT() asm volatile("cp.async.commit_group;" ::: "memory")

// ---------------------------------------------------------------------------
// K0: split pointwise weight into fp16 hi/lo (tiny)
// ---------------------------------------------------------------------------
__global__ __launch_bounds__(256) void k_splitW(const float* __restrict__ W)
{
    int i = blockIdx.x * 256 + threadIdx.x;
    float v = W[i];
    __half h = __float2half(v);
    g_wh[i] = h;
    g_wl[i] = __float2half(v - __half2float(h));
}

// ---------------------------------------------------------------------------
// K1: fused dwconv(3,5,7) + BN + GELU + average -> g_mid (fp16)
// One block per (b,c) plane. 70x70 haloed tile in smem. Also zeroes g_ssq.
// ---------------------------------------------------------------------------
__global__ __launch_bounds__(256) void k_dwconv(
    const float* __restrict__ x,
    const float* __restrict__ w3,
    const float* __restrict__ b3w, const float* __restrict__ b3b,
    const float* __restrict__ b3m, const float* __restrict__ b3v,
    const float* __restrict__ w5,
    const float* __restrict__ b5w, const float* __restrict__ b5b,
    const float* __restrict__ b5m, const float* __restrict__ b5v,
    const float* __restrict__ w7,
    const float* __restrict__ b7w, const float* __restrict__ b7b,
    const float* __restrict__ b7m, const float* __restrict__ b7v)
{
    __shared__ float tile[70 * 72];
    __shared__ float sw3[9], sw5[25], sw7[49];

    const int blk = blockIdx.x;        // b*256 + c
    const int c   = blk & 255;
    const int tid = threadIdx.x;

    if (tid == 0) g_ssq[blk] = 0.0f;

    const float* __restrict__ xp = x + (size_t)blk * HW;

    if (tid < 9)        sw3[tid]      = w3[c * 9 + tid];
    else if (tid < 34)  sw5[tid - 9]  = w5[c * 25 + (tid - 9)];
    else if (tid < 83)  sw7[tid - 34] = w7[c * 49 + (tid - 34)];

    for (int idx = tid; idx < 70 * 70; idx += 256) {
        int sy = idx / 70, sx = idx - sy * 70;
        int gy = sy - 3, gx = sx - 3;
        float v = 0.0f;
        if ((unsigned)gy < 64u && (unsigned)gx < 64u) v = xp[gy * 64 + gx];
        tile[sy * 72 + sx] = v;
    }

    const float sc3 = b3w[c] * rsqrtf(b3v[c] + 1e-5f);
    const float sh3 = b3b[c] - b3m[c] * sc3;
    const float sc5 = b5w[c] * rsqrtf(b5v[c] + 1e-5f);
    const float sh5 = b5b[c] - b5m[c] * sc5;
    const float sc7 = b7w[c] * rsqrtf(b7v[c] + 1e-5f);
    const float sh7 = b7b[c] - b7m[c] * sc7;

    __syncthreads();

    const int tx = tid & 15;
    const int r0 = tid >> 4;
    const float inv3 = (1.0f / 3.0f);

    #pragma unroll
    for (int rit = 0; rit < 4; rit++) {
        const int y = r0 + rit * 16;
        float a3[4] = {0.f, 0.f, 0.f, 0.f};
        float a5[4] = {0.f, 0.f, 0.f, 0.f};
        float a7[4] = {0.f, 0.f, 0.f, 0.f};

        #pragma unroll
        for (int ky = 0; ky < 7; ky++) {
            const float* rowp = &tile[(y + ky) * 72 + tx * 4];
            float4 v0 = *(const float4*)(rowp);
            float4 v1 = *(const float4*)(rowp + 4);
            float4 v2 = *(const float4*)(rowp + 8);
            float f[12];
            f[0]=v0.x; f[1]=v0.y; f[2]=v0.z; f[3]=v0.w;
            f[4]=v1.x; f[5]=v1.y; f[6]=v1.z; f[7]=v1.w;
            f[8]=v2.x; f[9]=v2.y; f[10]=v2.z; f[11]=v2.w;

            #pragma unroll
            for (int kx = 0; kx < 7; kx++) {
                const float w = sw7[ky * 7 + kx];
                #pragma unroll
                for (int j = 0; j < 4; j++) a7[j] += f[j + kx] * w;
            }
            if (ky >= 1 && ky <= 5) {
                #pragma unroll
                for (int kx = 0; kx < 5; kx++) {
                    const float w = sw5[(ky - 1) * 5 + kx];
                    #pragma unroll
                    for (int j = 0; j < 4; j++) a5[j] += f[j + 1 + kx] * w;
                }
            }
            if (ky >= 2 && ky <= 4) {
                #pragma unroll
                for (int kx = 0; kx < 3; kx++) {
                    const float w = sw3[(ky - 2) * 3 + kx];
                    #pragma unroll
                    for (int j = 0; j < 4; j++) a3[j] += f[j + 2 + kx] * w;
                }
            }
        }

        __half hh[4];
        #pragma unroll
        for (int j = 0; j < 4; j++) {
            float v = gelu_f(a3[j] * sc3 + sh3)
                    + gelu_f(a5[j] * sc5 + sh5)
                    + gelu_f(a7[j] * sc7 + sh7);
            hh[j] = __float2half(v * inv3);
        }
        size_t off = (size_t)blk * HW + y * 64 + tx * 4;
        ((__half2*)&g_mid[off])[0] = __halves2half2(hh[0], hh[1]);
        ((__half2*)&g_mid[off])[1] = __halves2half2(hh[2], hh[3]);
    }
}

// ---------------------------------------------------------------------------
// K2: mma.sync fp16 GEMM, split-fp16 W (2 terms), mid single fp16.
// Block tile 128(M=o) x 128(N=p), BK=32, 2-stage cp.async double buffer.
// 8 warps: 2(M) x 4(N), warp tile 64x32. Fused pwbn + ssq epilogue.
// ---------------------------------------------------------------------------
// dynamic smem layout (halves):
//   As[stage][comp][128][40]  : 2*2*128*40 = 20480 halves (40960 B)
//   Bs[stage][32][136]        : 2*32*136  =  8704 halves (17408 B)
#define AS_OFF(st, comp, m, k) (((st)*2 + (comp)) * (128*40) + (m)*40 + (k))
#define BS_OFF(st, k, n)       (20480 + (st)*(32*136) + (k)*136 + (n))
#define K2_DYNSMEM ((20480 + 8704) * 2)

__global__ __launch_bounds__(256) void k_pwgemm(
    const float* __restrict__ pbw, const float* __restrict__ pbb,
    const float* __restrict__ pbm, const float* __restrict__ pbv)
{
    extern __shared__ __half sm[];

    const int b     = blockIdx.z;
    const int nBase = blockIdx.x * 128;
    const int mBase = blockIdx.y * 128;

    const int tid  = threadIdx.x;
    const int lane = tid & 31;
    const int warp = tid >> 5;
    const int warp_m = warp >> 2;          // 0..1
    const int warp_n = warp & 3;           // 0..3

    const __half* __restrict__ Mb = g_mid + (size_t)b * Cc * HW;

    float acc[4][4][4];
    #pragma unroll
    for (int i = 0; i < 4; i++)
        #pragma unroll
        for (int j = 0; j < 4; j++)
            #pragma unroll
            for (int q = 0; q < 4; q++) acc[i][j][q] = 0.0f;

    // prefetch lambda: stage st, k-offset k0
    auto issue = [&](int st, int k0) {
        #pragma unroll
        for (int i = 0; i < 2; i++) {
            int e = i * 256 + tid;
            int row = e >> 2, seg = e & 3;
            size_t g = (size_t)(mBase + row) * 256 + k0 + seg * 8;
            CP_ASYNC16(smem_u32(&sm[AS_OFF(st, 0, row, seg * 8)]), &g_wh[g]);
            CP_ASYNC16(smem_u32(&sm[AS_OFF(st, 1, row, seg * 8)]), &g_wl[g]);
        }
        #pragma unroll
        for (int i = 0; i < 2; i++) {
            int e = i * 256 + tid;
            int row = e >> 4, seg = e & 15;
            CP_ASYNC16(smem_u32(&sm[BS_OFF(st, row, seg * 8)]),
                       &Mb[(size_t)(k0 + row) * HW + nBase + seg * 8]);
        }
    };

    issue(0, 0);
    CP_COMMIT();

    for (int s = 0; s < 8; s++) {
        if (s < 7) {
            issue((s + 1) & 1, (s + 1) * 32);
            CP_COMMIT();
            asm volatile("cp.async.wait_group 1;" ::: "memory");
        } else {
            asm volatile("cp.async.wait_group 0;" ::: "memory");
        }
        __syncthreads();

        const int st = s & 1;
        #pragma unroll
        for (int ks = 0; ks < 32; ks += 16) {
            u32 ah[4][4], al[4][4];
            const int a_m = warp_m * 64 + (lane & 15);
            const int a_k = ks + ((lane >> 4) << 3);
            #pragma unroll
            for (int fm = 0; fm < 4; fm++) {
                ldsm_x4(ah[fm][0], ah[fm][1], ah[fm][2], ah[fm][3],
                        smem_u32(&sm[AS_OFF(st, 0, a_m + fm * 16, a_k)]));
                ldsm_x4(al[fm][0], al[fm][1], al[fm][2], al[fm][3],
                        smem_u32(&sm[AS_OFF(st, 1, a_m + fm * 16, a_k)]));
            }
            u32 bq[4][2];
            const int b_k = ks + (lane & 15);
            const int b_n = warp_n * 32 + ((lane >> 4) << 3);
            #pragma unroll
            for (int g = 0; g < 2; g++) {
                u32 r0, r1, r2, r3;
                ldsm_x4t(r0, r1, r2, r3,
                         smem_u32(&sm[BS_OFF(st, b_k, b_n + g * 16)]));
                bq[g*2][0] = r0; bq[g*2][1] = r1;
                bq[g*2+1][0] = r2; bq[g*2+1][1] = r3;
            }
            #pragma unroll
            for (int fm = 0; fm < 4; fm++)
                #pragma unroll
                for (int fn = 0; fn < 4; fn++) {
                    mma_f16(acc[fm][fn], ah[fm], bq[fn]);
                    mma_f16(acc[fm][fn], al[fm], bq[fn]);
                }
        }
        __syncthreads();
    }

    // Epilogue: pwbn + store + ssq
    float* __restrict__ yb = g_y + (size_t)b * Cc * HW;
    const int row  = lane >> 2;
    const int colq = (lane & 3) * 2;

    #pragma unroll
    for (int fm = 0; fm < 4; fm++) {
        const int o0 = mBase + warp_m * 64 + fm * 16 + row;
        const int o1 = o0 + 8;
        const float sc0 = pbw[o0] * rsqrtf(pbv[o0] + 1e-5f);
        const float sh0 = pbb[o0] - pbm[o0] * sc0;
        const float sc1 = pbw[o1] * rsqrtf(pbv[o1] + 1e-5f);
        const float sh1 = pbb[o1] - pbm[o1] * sc1;
        float ss0 = 0.0f, ss1 = 0.0f;
        #pragma unroll
        for (int fn = 0; fn < 4; fn++) {
            const int p = nBase + warp_n * 32 + fn * 8 + colq;
            float v0 = acc[fm][fn][0] * sc0 + sh0;
            float v1 = acc[fm][fn][1] * sc0 + sh0;
            float v2 = acc[fm][fn][2] * sc1 + sh1;
            float v3 = acc[fm][fn][3] * sc1 + sh1;
            ss0 += v0 * v0 + v1 * v1;
            ss1 += v2 * v2 + v3 * v3;
            *(float2*)&yb[(size_t)o0 * HW + p] = make_float2(v0, v1);
            *(float2*)&yb[(size_t)o1 * HW + p] = make_float2(v2, v3);
        }
        ss0 += __shfl_xor_sync(0xffffffffu, ss0, 1);
        ss0 += __shfl_xor_sync(0xffffffffu, ss0, 2);
        ss1 += __shfl_xor_sync(0xffffffffu, ss1, 1);
        ss1 += __shfl_xor_sync(0xffffffffu, ss1, 2);
        if ((lane & 3) == 0) {
            atomicAdd(&g_ssq[b * Cc + o0], ss0);
            atomicAdd(&g_ssq[b * Cc + o1], ss1);
        }
    }
}

// ---------------------------------------------------------------------------
// K3: GRN factor per (b,c)
// ---------------------------------------------------------------------------
__global__ __launch_bounds__(256) void k_grn(const float* __restrict__ gamma)
{
    __shared__ float sh[256];
    const int b = blockIdx.x;
    const int c = threadIdx.x;
    const float Gx = sqrtf(g_ssq[b * Cc + c]);
    sh[c] = Gx;
    __syncthreads();
    #pragma unroll
    for (int s = 128; s > 0; s >>= 1) {
        if (c < s) sh[c] += sh[c + s];
        __syncthreads();
    }
    const float mean = sh[0] * (1.0f / 256.0f);
    const float Nx = Gx / (mean + 1e-6f);
    g_a[b * Cc + c] = 1.0f + gamma[c] * Nx;
}

// ---------------------------------------------------------------------------
// K4: out = gelu(y * a[b,c] + beta[c] + x)
// ---------------------------------------------------------------------------
__global__ __launch_bounds__(256) void k_final(
    const float* __restrict__ x,
    const float* __restrict__ beta,
    float* __restrict__ out)
{
    const int i4 = blockIdx.x * 256 + threadIdx.x;
    const int bc = i4 >> 10;
    const int c  = bc & 255;
    const float a  = g_a[bc];
    const float bt = beta[c];
    float4 yv = ((const float4*)g_y)[i4];
    float4 xv = ((const float4*)x)[i4];
    float4 ov;
    ov.x = gelu_f(yv.x * a + bt + xv.x);
    ov.y = gelu_f(yv.y * a + bt + xv.y);
    ov.z = gelu_f(yv.z * a + bt + xv.z);
    ov.w = gelu_f(yv.w * a + bt + xv.w);
    ((float4*)out)[i4] = ov;
}

// ---------------------------------------------------------------------------
extern "C" void kernel_launch(void* const* d_in, const int* in_sizes, int n_in,
                              void* d_out, int out_size)
{
    const float* x    = (const float*)d_in[0];
    const float* w3   = (const float*)d_in[1];
    const float* b3w  = (const float*)d_in[2];
    const float* b3b  = (const float*)d_in[3];
    const float* b3m  = (const float*)d_in[4];
    const float* b3v  = (const float*)d_in[5];
    const float* w5   = (const float*)d_in[6];
    const float* b5w  = (const float*)d_in[7];
    const float* b5b  = (const float*)d_in[8];
    const float* b5m  = (const float*)d_in[9];
    const float* b5v  = (const float*)d_in[10];
    const float* w7   = (const float*)d_in[11];
    const float* b7w  = (const float*)d_in[12];
    const float* b7b  = (const float*)d_in[13];
    const float* b7m  = (const float*)d_in[14];
    const float* b7v  = (const float*)d_in[15];
    const float* pw   = (const float*)d_in[16];
    const float* pbw  = (const float*)d_in[17];
    const float* pbb  = (const float*)d_in[18];
    const float* pbm  = (const float*)d_in[19];
    const float* pbv  = (const float*)d_in[20];
    const float* grng = (const float*)d_in[21];
    const float* grnb = (const float*)d_in[22];

    cudaFuncSetAttribute(k_pwgemm,
                         cudaFuncAttributeMaxDynamicSharedMemorySize, K2_DYNSMEM);

    k_splitW<<<Cc * Cc / 256, 256>>>(pw);

    k_dwconv<<<Bb * Cc, 256>>>(x, w3, b3w, b3b, b3m, b3v,
                               w5, b5w, b5b, b5m, b5v,
                               w7, b7w, b7b, b7m, b7v);

    dim3 g2(HW / 128, Cc / 128, Bb);   // (32, 2, 32)
    k_pwgemm<<<g2, 256, K2_DYNSMEM>>>(pbw, pbb, pbm, pbv);

    k_grn<<<Bb, 256>>>(grng);

    k_final<<<NTOT / 4 / 256, 256>>>(x, grnb, (float*)d_out);
}

// round 6
// speedup vs baseline: 1.7374x; 1.0711x over previous
#include <cuda_runtime.h>
#include <cuda_fp16.h>
#include <stdint.h>
#include <math.h>

#define Bb 32
#define Cc 256
#define Hh 64
#define Ww 64
#define HW 4096
#define NTOT (Bb*Cc*HW)

typedef unsigned int u32;

// Scratch (allocation-free rule: __device__ globals)
__device__ __half g_mid[NTOT];         // 64 MB: dwconv output, fp16
__device__ __half g_wh[Cc*Cc];         // pointwise W, fp16
__device__ float g_y[NTOT];            // 128 MB: post-pointwise+pwbn
__device__ float g_ssq[Bb*Cc];         // per-(b,c) sum of squares
__device__ float g_a[Bb*Cc];           // GRN multiplicative factor

__device__ __forceinline__ float gelu_f(float v) {
    return 0.5f * v * (1.0f + erff(v * 0.7071067811865475f));
}

__device__ __forceinline__ u32 smem_u32(const void* p) {
    return (u32)__cvta_generic_to_shared(p);
}

__device__ __forceinline__ void ldsm_x4(u32& r0, u32& r1, u32& r2, u32& r3, u32 a) {
    asm volatile("ldmatrix.sync.aligned.m8n8.x4.shared.b16 {%0,%1,%2,%3},[%4];\n"
                 : "=r"(r0), "=r"(r1), "=r"(r2), "=r"(r3) : "r"(a));
}
__device__ __forceinline__ void ldsm_x4t(u32& r0, u32& r1, u32& r2, u32& r3, u32 a) {
    asm volatile("ldmatrix.sync.aligned.m8n8.x4.trans.shared.b16 {%0,%1,%2,%3},[%4];\n"
                 : "=r"(r0), "=r"(r1), "=r"(r2), "=r"(r3) : "r"(a));
}
__device__ __forceinline__ void mma_f16(float* c, const u32* a, const u32* bq) {
    asm volatile(
        "mma.sync.aligned.m16n8k16.row.col.f32.f16.f16.f32 "
        "{%0,%1,%2,%3},{%4,%5,%6,%7},{%8,%9},{%0,%1,%2,%3};\n"
        : "+f"(c[0]), "+f"(c[1]), "+f"(c[2]), "+f"(c[3])
        : "r"(a[0]), "r"(a[1]), "r"(a[2]), "r"(a[3]), "r"(bq[0]), "r"(bq[1]));
}

#define CP_ASYNC16(dst, src) \
    asm volatile("cp.async.cg.shared.global [%0], [%1], 16;" :: "r"(dst), "l"(src))
#define CP_COMMIT() asm volatile("cp.async.commit_group;" ::: "memory")

// ---------------------------------------------------------------------------
// K0: convert pointwise weight to fp16 (tiny)
// ---------------------------------------------------------------------------
__global__ __launch_bounds__(256) void k_cvtW(const float* __restrict__ W)
{
    int i = blockIdx.x * 256 + threadIdx.x;
    g_wh[i] = __float2half(W[i]);
}

// ---------------------------------------------------------------------------
// K1: fused dwconv(3,5,7) + BN + GELU + average -> g_mid (fp16)
// One block per (b,c) plane. 70x70 haloed tile in smem. Also zeroes g_ssq.
// ---------------------------------------------------------------------------
__global__ __launch_bounds__(256) void k_dwconv(
    const float* __restrict__ x,
    const float* __restrict__ w3,
    const float* __restrict__ b3w, const float* __restrict__ b3b,
    const float* __restrict__ b3m, const float* __restrict__ b3v,
    const float* __restrict__ w5,
    const float* __restrict__ b5w, const float* __restrict__ b5b,
    const float* __restrict__ b5m, const float* __restrict__ b5v,
    const float* __restrict__ w7,
    const float* __restrict__ b7w, const float* __restrict__ b7b,
    const float* __restrict__ b7m, const float* __restrict__ b7v)
{
    __shared__ float tile[70 * 72];
    __shared__ float sw3[9], sw5[25], sw7[49];

    const int blk = blockIdx.x;        // b*256 + c
    const int c   = blk & 255;
    const int tid = threadIdx.x;

    if (tid == 0) g_ssq[blk] = 0.0f;

    const float* __restrict__ xp = x + (size_t)blk * HW;

    if (tid < 9)        sw3[tid]      = w3[c * 9 + tid];
    else if (tid < 34)  sw5[tid - 9]  = w5[c * 25 + (tid - 9)];
    else if (tid < 83)  sw7[tid - 34] = w7[c * 49 + (tid - 34)];

    for (int idx = tid; idx < 70 * 70; idx += 256) {
        int sy = idx / 70, sx = idx - sy * 70;
        int gy = sy - 3, gx = sx - 3;
        float v = 0.0f;
        if ((unsigned)gy < 64u && (unsigned)gx < 64u) v = xp[gy * 64 + gx];
        tile[sy * 72 + sx] = v;
    }

    const float sc3 = b3w[c] * rsqrtf(b3v[c] + 1e-5f);
    const float sh3 = b3b[c] - b3m[c] * sc3;
    const float sc5 = b5w[c] * rsqrtf(b5v[c] + 1e-5f);
    const float sh5 = b5b[c] - b5m[c] * sc5;
    const float sc7 = b7w[c] * rsqrtf(b7v[c] + 1e-5f);
    const float sh7 = b7b[c] - b7m[c] * sc7;

    __syncthreads();

    const int tx = tid & 15;
    const int r0 = tid >> 4;
    const float inv3 = (1.0f / 3.0f);

    #pragma unroll
    for (int rit = 0; rit < 4; rit++) {
        const int y = r0 + rit * 16;
        float a3[4] = {0.f, 0.f, 0.f, 0.f};
        float a5[4] = {0.f, 0.f, 0.f, 0.f};
        float a7[4] = {0.f, 0.f, 0.f, 0.f};

        #pragma unroll
        for (int ky = 0; ky < 7; ky++) {
            const float* rowp = &tile[(y + ky) * 72 + tx * 4];
            float4 v0 = *(const float4*)(rowp);
            float4 v1 = *(const float4*)(rowp + 4);
            float4 v2 = *(const float4*)(rowp + 8);
            float f[12];
            f[0]=v0.x; f[1]=v0.y; f[2]=v0.z; f[3]=v0.w;
            f[4]=v1.x; f[5]=v1.y; f[6]=v1.z; f[7]=v1.w;
            f[8]=v2.x; f[9]=v2.y; f[10]=v2.z; f[11]=v2.w;

            #pragma unroll
            for (int kx = 0; kx < 7; kx++) {
                const float w = sw7[ky * 7 + kx];
                #pragma unroll
                for (int j = 0; j < 4; j++) a7[j] += f[j + kx] * w;
            }
            if (ky >= 1 && ky <= 5) {
                #pragma unroll
                for (int kx = 0; kx < 5; kx++) {
                    const float w = sw5[(ky - 1) * 5 + kx];
                    #pragma unroll
                    for (int j = 0; j < 4; j++) a5[j] += f[j + 1 + kx] * w;
                }
            }
            if (ky >= 2 && ky <= 4) {
                #pragma unroll
                for (int kx = 0; kx < 3; kx++) {
                    const float w = sw3[(ky - 2) * 3 + kx];
                    #pragma unroll
                    for (int j = 0; j < 4; j++) a3[j] += f[j + 2 + kx] * w;
                }
            }
        }

        __half hh[4];
        #pragma unroll
        for (int j = 0; j < 4; j++) {
            float v = gelu_f(a3[j] * sc3 + sh3)
                    + gelu_f(a5[j] * sc5 + sh5)
                    + gelu_f(a7[j] * sc7 + sh7);
            hh[j] = __float2half(v * inv3);
        }
        size_t off = (size_t)blk * HW + y * 64 + tx * 4;
        ((__half2*)&g_mid[off])[0] = __halves2half2(hh[0], hh[1]);
        ((__half2*)&g_mid[off])[1] = __halves2half2(hh[2], hh[3]);
    }
}

// ---------------------------------------------------------------------------
// K2: mma.sync fp16 GEMM, single term (W fp16, mid fp16).
// Block tile 128(M=o) x 128(N=p), BK=32, 2-stage cp.async double buffer.
// 8 warps: 2(M) x 4(N), warp tile 64x32. Fused pwbn + ssq epilogue.
// ---------------------------------------------------------------------------
// dynamic smem layout (halves):
//   As[stage][128][40]  : 2*128*40 = 10240 halves (20480 B)
//   Bs[stage][32][136]  : 2*32*136 =  8704 halves (17408 B)
#define AS_OFF(st, m, k) ((st) * (128*40) + (m)*40 + (k))
#define BS_OFF(st, k, n) (10240 + (st)*(32*136) + (k)*136 + (n))
#define K2_DYNSMEM ((10240 + 8704) * 2)

__global__ __launch_bounds__(256) void k_pwgemm(
    const float* __restrict__ pbw, const float* __restrict__ pbb,
    const float* __restrict__ pbm, const float* __restrict__ pbv)
{
    extern __shared__ __half sm[];

    const int b     = blockIdx.z;
    const int nBase = blockIdx.x * 128;
    const int mBase = blockIdx.y * 128;

    const int tid  = threadIdx.x;
    const int lane = tid & 31;
    const int warp = tid >> 5;
    const int warp_m = warp >> 2;          // 0..1
    const int warp_n = warp & 3;           // 0..3

    const __half* __restrict__ Mb = g_mid + (size_t)b * Cc * HW;

    float acc[4][4][4];
    #pragma unroll
    for (int i = 0; i < 4; i++)
        #pragma unroll
        for (int j = 0; j < 4; j++)
            #pragma unroll
            for (int q = 0; q < 4; q++) acc[i][j][q] = 0.0f;

    // prefetch: stage st, k-offset k0
    auto issue = [&](int st, int k0) {
        #pragma unroll
        for (int i = 0; i < 2; i++) {
            int e = i * 256 + tid;
            int row = e >> 2, seg = e & 3;
            CP_ASYNC16(smem_u32(&sm[AS_OFF(st, row, seg * 8)]),
                       &g_wh[(size_t)(mBase + row) * 256 + k0 + seg * 8]);
        }
        #pragma unroll
        for (int i = 0; i < 2; i++) {
            int e = i * 256 + tid;
            int row = e >> 4, seg = e & 15;
            CP_ASYNC16(smem_u32(&sm[BS_OFF(st, row, seg * 8)]),
                       &Mb[(size_t)(k0 + row) * HW + nBase + seg * 8]);
        }
    };

    issue(0, 0);
    CP_COMMIT();

    for (int s = 0; s < 8; s++) {
        if (s < 7) {
            issue((s + 1) & 1, (s + 1) * 32);
            CP_COMMIT();
            asm volatile("cp.async.wait_group 1;" ::: "memory");
        } else {
            asm volatile("cp.async.wait_group 0;" ::: "memory");
        }
        __syncthreads();

        const int st = s & 1;
        #pragma unroll
        for (int ks = 0; ks < 32; ks += 16) {
            u32 ah[4][4];
            const int a_m = warp_m * 64 + (lane & 15);
            const int a_k = ks + ((lane >> 4) << 3);
            #pragma unroll
            for (int fm = 0; fm < 4; fm++) {
                ldsm_x4(ah[fm][0], ah[fm][1], ah[fm][2], ah[fm][3],
                        smem_u32(&sm[AS_OFF(st, a_m + fm * 16, a_k)]));
            }
            u32 bq[4][2];
            const int b_k = ks + (lane & 15);
            const int b_n = warp_n * 32 + ((lane >> 4) << 3);
            #pragma unroll
            for (int g = 0; g < 2; g++) {
                u32 r0, r1, r2, r3;
                ldsm_x4t(r0, r1, r2, r3,
                         smem_u32(&sm[BS_OFF(st, b_k, b_n + g * 16)]));
                bq[g*2][0] = r0; bq[g*2][1] = r1;
                bq[g*2+1][0] = r2; bq[g*2+1][1] = r3;
            }
            #pragma unroll
            for (int fm = 0; fm < 4; fm++)
                #pragma unroll
                for (int fn = 0; fn < 4; fn++)
                    mma_f16(acc[fm][fn], ah[fm], bq[fn]);
        }
        __syncthreads();
    }

    // Epilogue: pwbn + store + ssq
    float* __restrict__ yb = g_y + (size_t)b * Cc * HW;
    const int row  = lane >> 2;
    const int colq = (lane & 3) * 2;

    #pragma unroll
    for (int fm = 0; fm < 4; fm++) {
        const int o0 = mBase + warp_m * 64 + fm * 16 + row;
        const int o1 = o0 + 8;
        const float sc0 = pbw[o0] * rsqrtf(pbv[o0] + 1e-5f);
        const float sh0 = pbb[o0] - pbm[o0] * sc0;
        const float sc1 = pbw[o1] * rsqrtf(pbv[o1] + 1e-5f);
        const float sh1 = pbb[o1] - pbm[o1] * sc1;
        float ss0 = 0.0f, ss1 = 0.0f;
        #pragma unroll
        for (int fn = 0; fn < 4; fn++) {
            const int p = nBase + warp_n * 32 + fn * 8 + colq;
            float v0 = acc[fm][fn][0] * sc0 + sh0;
            float v1 = acc[fm][fn][1] * sc0 + sh0;
            float v2 = acc[fm][fn][2] * sc1 + sh1;
            float v3 = acc[fm][fn][3] * sc1 + sh1;
            ss0 += v0 * v0 + v1 * v1;
            ss1 += v2 * v2 + v3 * v3;
            *(float2*)&yb[(size_t)o0 * HW + p] = make_float2(v0, v1);
            *(float2*)&yb[(size_t)o1 * HW + p] = make_float2(v2, v3);
        }
        ss0 += __shfl_xor_sync(0xffffffffu, ss0, 1);
        ss0 += __shfl_xor_sync(0xffffffffu, ss0, 2);
        ss1 += __shfl_xor_sync(0xffffffffu, ss1, 1);
        ss1 += __shfl_xor_sync(0xffffffffu, ss1, 2);
        if ((lane & 3) == 0) {
            atomicAdd(&g_ssq[b * Cc + o0], ss0);
            atomicAdd(&g_ssq[b * Cc + o1], ss1);
        }
    }
}

// ---------------------------------------------------------------------------
// K3: GRN factor per (b,c)
// ---------------------------------------------------------------------------
__global__ __launch_bounds__(256) void k_grn(const float* __restrict__ gamma)
{
    __shared__ float sh[256];
    const int b = blockIdx.x;
    const int c = threadIdx.x;
    const float Gx = sqrtf(g_ssq[b * Cc + c]);
    sh[c] = Gx;
    __syncthreads();
    #pragma unroll
    for (int s = 128; s > 0; s >>= 1) {
        if (c < s) sh[c] += sh[c + s];
        __syncthreads();
    }
    const float mean = sh[0] * (1.0f / 256.0f);
    const float Nx = Gx / (mean + 1e-6f);
    g_a[b * Cc + c] = 1.0f + gamma[c] * Nx;
}

// ---------------------------------------------------------------------------
// K4: out = gelu(y * a[b,c] + beta[c] + x)
// ---------------------------------------------------------------------------
__global__ __launch_bounds__(256) void k_final(
    const float* __restrict__ x,
    const float* __restrict__ beta,
    float* __restrict__ out)
{
    const int i4 = blockIdx.x * 256 + threadIdx.x;
    const int bc = i4 >> 10;
    const int c  = bc & 255;
    const float a  = g_a[bc];
    const float bt = beta[c];
    float4 yv = ((const float4*)g_y)[i4];
    float4 xv = ((const float4*)x)[i4];
    float4 ov;
    ov.x = gelu_f(yv.x * a + bt + xv.x);
    ov.y = gelu_f(yv.y * a + bt + xv.y);
    ov.z = gelu_f(yv.z * a + bt + xv.z);
    ov.w = gelu_f(yv.w * a + bt + xv.w);
    ((float4*)out)[i4] = ov;
}

// ---------------------------------------------------------------------------
extern "C" void kernel_launch(void* const* d_in, const int* in_sizes, int n_in,
                              void* d_out, int out_size)
{
    const float* x    = (const float*)d_in[0];
    const float* w3   = (const float*)d_in[1];
    const float* b3w  = (const float*)d_in[2];
    const float* b3b  = (const float*)d_in[3];
    const float* b3m  = (const float*)d_in[4];
    const float* b3v  = (const float*)d_in[5];
    const float* w5   = (const float*)d_in[6];
    const float* b5w  = (const float*)d_in[7];
    const float* b5b  = (const float*)d_in[8];
    const float* b5m  = (const float*)d_in[9];
    const float* b5v  = (const float*)d_in[10];
    const float* w7   = (const float*)d_in[11];
    const float* b7w  = (const float*)d_in[12];
    const float* b7b  = (const float*)d_in[13];
    const float* b7m  = (const float*)d_in[14];
    const float* b7v  = (const float*)d_in[15];
    const float* pw   = (const float*)d_in[16];
    const float* pbw  = (const float*)d_in[17];
    const float* pbb  = (const float*)d_in[18];
    const float* pbm  = (const float*)d_in[19];
    const float* pbv  = (const float*)d_in[20];
    const float* grng = (const float*)d_in[21];
    const float* grnb = (const float*)d_in[22];

    cudaFuncSetAttribute(k_pwgemm,
                         cudaFuncAttributeMaxDynamicSharedMemorySize, K2_DYNSMEM);

    k_cvtW<<<Cc * Cc / 256, 256>>>(pw);

    k_dwconv<<<Bb * Cc, 256>>>(x, w3, b3w, b3b, b3m, b3v,
                               w5, b5w, b5b, b5m, b5v,
                               w7, b7w, b7b, b7m, b7v);

    dim3 g2(HW / 128, Cc / 128, Bb);   // (32, 2, 32)
    k_pwgemm<<<g2, 256, K2_DYNSMEM>>>(pbw, pbb, pbm, pbv);

    k_grn<<<Bb, 256>>>(grng);

    k_final<<<NTOT / 4 / 256, 256>>>(x, grnb, (float*)d_out);
}